// round 2
// baseline (speedup 1.0000x reference)
#include <cuda_runtime.h>

#define FULL 0xffffffffu
#define PI_4 0.78539816339744830962f

__device__ __forceinline__ float fast_tanh(float x) {
    // tanh(x) = (e^{2x}-1)/(e^{2x}+1); inputs here are ~N(0,1), well in range
    float e = __expf(2.0f * x);
    return (e - 1.0f) / (e + 1.0f);
}

// ---- RY on a local (register) bit: pairs r <-> r|(1<<BIT) ----
template<int BIT>
__device__ __forceinline__ void ry_local(float (&s)[32], float c, float si) {
#pragma unroll
    for (int r = 0; r < 32; r++) {
        if (!((r >> BIT) & 1)) {
            float a0 = s[r], a1 = s[r + (1 << BIT)];
            s[r]              = fmaf(c,  a0, -si * a1);
            s[r + (1 << BIT)] = fmaf(si, a0,  c  * a1);
        }
    }
}

// ---- RY on a lane bit: partner via shfl_xor, sign by own bit ----
template<int LB>
__device__ __forceinline__ void ry_lane(float (&s)[32], float c, float si, int lane) {
    float sg = ((lane >> LB) & 1) ? si : -si;
#pragma unroll
    for (int r = 0; r < 32; r++) {
        float p = __shfl_xor_sync(FULL, s[r], 1 << LB);
        s[r] = fmaf(c, s[r], sg * p);
    }
}

// ---- CNOT, control lane bit CB, target lane bit TB ----
template<int CB, int TB>
__device__ __forceinline__ void cnot_ll(float (&s)[32], int lane) {
    bool ctl = (lane >> CB) & 1;
#pragma unroll
    for (int r = 0; r < 32; r++) {
        float p = __shfl_xor_sync(FULL, s[r], 1 << TB);
        s[r] = ctl ? p : s[r];
    }
}

// ---- CNOT, control lane bit CB, target local bit TB ----
template<int CB, int TB>
__device__ __forceinline__ void cnot_lloc(float (&s)[32], int lane) {
    bool ctl = (lane >> CB) & 1;
#pragma unroll
    for (int r = 0; r < 32; r++) {
        if (!((r >> TB) & 1)) {
            float a = s[r], b = s[r + (1 << TB)];
            s[r]              = ctl ? b : a;
            s[r + (1 << TB)]  = ctl ? a : b;
        }
    }
}

// ---- CNOT, both local bits (compile-time register permutation, ~free) ----
template<int CB, int TB>
__device__ __forceinline__ void cnot_loc(float (&s)[32]) {
#pragma unroll
    for (int r = 0; r < 32; r++) {
        if (((r >> CB) & 1) && !((r >> TB) & 1)) {
            float t = s[r];
            s[r] = s[r + (1 << TB)];
            s[r + (1 << TB)] = t;
        }
    }
}

// One full RY layer over 10 wires.
// Wire w acts on amplitude-index bit (9-w): wires 0..4 -> lane bits 4..0,
// wires 5..9 -> local bits 4..0.
__device__ __forceinline__ void ry_layer(float (&s)[32], const float2 (&g)[10], int lane) {
    ry_lane<4>(s, g[0].x, g[0].y, lane);
    ry_lane<3>(s, g[1].x, g[1].y, lane);
    ry_lane<2>(s, g[2].x, g[2].y, lane);
    ry_lane<1>(s, g[3].x, g[3].y, lane);
    ry_lane<0>(s, g[4].x, g[4].y, lane);
    ry_local<4>(s, g[5].x, g[5].y);
    ry_local<3>(s, g[6].x, g[6].y);
    ry_local<2>(s, g[7].x, g[7].y);
    ry_local<1>(s, g[8].x, g[8].y);
    ry_local<0>(s, g[9].x, g[9].y);
}

__global__ __launch_bounds__(256, 2)
void hybrid_head_kernel(const float* __restrict__ X,       // (B,512)
                        const float* __restrict__ Wpre,    // (10,512)
                        const float* __restrict__ bpre,    // (10,)
                        const float* __restrict__ qp,      // (150,)
                        const float* __restrict__ Wpost,   // (2,10)
                        const float* __restrict__ bpost,   // (2,)
                        float* __restrict__ out,           // (B,2)
                        int B)
{
    __shared__ float2 cs_sh[6][10];   // cos/sin of shared-layer half-angles

    const int tid = threadIdx.x;
    if (tid < 60) {
        int k = tid / 10, w = tid % 10;
        float th = 0.5f * qp[(k + 1) * 10 + w];
        cs_sh[k][w] = make_float2(cosf(th), sinf(th));
    }
    __syncthreads();

    const int lane   = tid & 31;
    const int sample = blockIdx.x * 8 + (tid >> 5);
    if (sample >= B) return;

    // ---------------- pre-GEMM: acc[w] = X[sample] . Wpre[w] ----------------
    float acc[10];
#pragma unroll
    for (int w = 0; w < 10; w++) acc[w] = 0.0f;

    const float4* Xr = reinterpret_cast<const float4*>(X + (size_t)sample * 512);
    float4 xv[4];
#pragma unroll
    for (int j = 0; j < 4; j++) xv[j] = Xr[j * 32 + lane];

#pragma unroll
    for (int w = 0; w < 10; w++) {
        const float4* Wr = reinterpret_cast<const float4*>(Wpre + w * 512);
#pragma unroll
        for (int j = 0; j < 4; j++) {
            float4 wv = Wr[j * 32 + lane];
            acc[w] = fmaf(xv[j].x, wv.x, acc[w]);
            acc[w] = fmaf(xv[j].y, wv.y, acc[w]);
            acc[w] = fmaf(xv[j].z, wv.z, acc[w]);
            acc[w] = fmaf(xv[j].w, wv.w, acc[w]);
        }
    }
#pragma unroll
    for (int w = 0; w < 10; w++) {
#pragma unroll
        for (int o = 16; o > 0; o >>= 1)
            acc[w] += __shfl_xor_sync(FULL, acc[w], o);
    }

    // lane w (w<10) owns wire w's input angle; others compute wire 0 redundantly
    float myc, mys;
    {
        float x = acc[0] + bpre[0];
#pragma unroll
        for (int w = 1; w < 10; w++) {
            float xw = acc[w] + bpre[w];
            x = (lane == w) ? xw : x;
        }
        float th = fast_tanh(x) * PI_4;    // theta/2 = tanh(pre)*pi/4
        myc = __cosf(th);
        mys = __sinf(th);
    }

    // ---------------- quantum circuit ----------------
    float s[32];
#pragma unroll
    for (int r = 0; r < 32; r++) s[r] = 0.03125f;   // H^{x10}|0..0> = uniform 1/32

    // per-sample RY layer (angles broadcast from owning lanes)
    {
        float2 g[10];
#pragma unroll
        for (int w = 0; w < 10; w++) {
            g[w].x = __shfl_sync(FULL, myc, w);
            g[w].y = __shfl_sync(FULL, mys, w);
        }
        ry_layer(s, g, lane);
    }

    // 6 entangling layers; keep loop rolled to limit I$ footprint
#pragma unroll 1
    for (int k = 0; k < 6; k++) {
        // even CNOT pairs (0,1)(2,3)(4,5)(6,7)(8,9)
        cnot_ll<4, 3>(s, lane);
        cnot_ll<2, 1>(s, lane);
        cnot_lloc<0, 4>(s, lane);
        cnot_loc<3, 2>(s);
        cnot_loc<1, 0>(s);
        // odd CNOT pairs (1,2)(3,4)(5,6)(7,8)
        cnot_ll<3, 2>(s, lane);
        cnot_ll<1, 0>(s, lane);
        cnot_loc<4, 3>(s);
        cnot_loc<2, 1>(s);
        // shared RY layer k (row k+1 of q_params)
        float2 g[10];
#pragma unroll
        for (int w = 0; w < 10; w++) g[w] = cs_sh[k][w];
        ry_layer(s, g, lane);
    }

    // ---------------- <Z_w> via signed-sum tree over probs ----------------
    float p[32];
#pragma unroll
    for (int r = 0; r < 32; r++) p[r] = s[r] * s[r];

    float a16[16], a8[8], a4[4], a2[2];
    float zb0 = 0.f, zb1 = 0.f, zb2 = 0.f, zb3 = 0.f;
#pragma unroll
    for (int i = 0; i < 16; i++) { a16[i] = p[2*i] + p[2*i+1]; zb0 += p[2*i] - p[2*i+1]; }
#pragma unroll
    for (int i = 0; i < 8;  i++) { a8[i]  = a16[2*i] + a16[2*i+1]; zb1 += a16[2*i] - a16[2*i+1]; }
#pragma unroll
    for (int i = 0; i < 4;  i++) { a4[i]  = a8[2*i] + a8[2*i+1];  zb2 += a8[2*i] - a8[2*i+1]; }
#pragma unroll
    for (int i = 0; i < 2;  i++) { a2[i]  = a4[2*i] + a4[2*i+1];  zb3 += a4[2*i] - a4[2*i+1]; }
    float T   = a2[0] + a2[1];
    float zb4 = a2[0] - a2[1];

    float z[10];
    z[0] = (lane & 16) ? -T : T;   // wire 0 -> lane bit 4
    z[1] = (lane & 8)  ? -T : T;
    z[2] = (lane & 4)  ? -T : T;
    z[3] = (lane & 2)  ? -T : T;
    z[4] = (lane & 1)  ? -T : T;
    z[5] = zb4;                    // wire 5 -> local bit 4
    z[6] = zb3;
    z[7] = zb2;
    z[8] = zb1;
    z[9] = zb0;

#pragma unroll
    for (int w = 0; w < 10; w++) {
#pragma unroll
        for (int o = 16; o > 0; o >>= 1)
            z[w] += __shfl_xor_sync(FULL, z[w], o);
    }

    // ---------------- post-GEMM ----------------
    if (lane == 0) {
        float o0 = bpost[0], o1 = bpost[1];
#pragma unroll
        for (int w = 0; w < 10; w++) {
            o0 = fmaf(z[w], Wpost[w],      o0);
            o1 = fmaf(z[w], Wpost[10 + w], o1);
        }
        reinterpret_cast<float2*>(out)[sample] = make_float2(o0, o1);
    }
}

extern "C" void kernel_launch(void* const* d_in, const int* in_sizes, int n_in,
                              void* d_out, int out_size)
{
    const float* X     = (const float*)d_in[0];
    const float* Wpre  = (const float*)d_in[1];
    const float* bpre  = (const float*)d_in[2];
    const float* qp    = (const float*)d_in[3];
    const float* Wpost = (const float*)d_in[4];
    const float* bpost = (const float*)d_in[5];
    float* out = (float*)d_out;

    int B = in_sizes[0] / 512;           // 8192
    int blocks = (B + 7) / 8;            // 8 samples (warps) per 256-thread block
    hybrid_head_kernel<<<blocks, 256>>>(X, Wpre, bpre, qp, Wpost, bpost, out, B);
}

// round 5
// speedup vs baseline: 1.1933x; 1.1933x over previous
#include <cuda_runtime.h>

typedef unsigned long long ull;
#define FULL 0xffffffffu
#define PI_4 0.78539816339744830962f

// ---------------- packed f32x2 helpers (Blackwell FFMA2/FMUL2 path) ----------------
__device__ __forceinline__ ull pk(float a, float b) {
    ull r; asm("mov.b64 %0, {%1,%2};" : "=l"(r) : "f"(a), "f"(b)); return r;
}
__device__ __forceinline__ void upk(ull v, float &a, float &b) {
    asm("mov.b64 {%0,%1}, %2;" : "=f"(a), "=f"(b) : "l"(v));
}
__device__ __forceinline__ ull fma2(ull a, ull b, ull c) {
    ull d; asm("fma.rn.f32x2 %0, %1, %2, %3;" : "=l"(d) : "l"(a), "l"(b), "l"(c)); return d;
}
__device__ __forceinline__ ull mul2(ull a, ull b) {
    ull d; asm("mul.rn.f32x2 %0, %1, %2;" : "=l"(d) : "l"(a), "l"(b)); return d;
}
__device__ __forceinline__ ull swp(ull v) {            // swap packed halves
    unsigned lo = (unsigned)v, hi = (unsigned)(v >> 32);
    return ((ull)lo << 32) | hi;
}

__device__ __forceinline__ float fast_tanh(float x) {
    float e = __expf(2.0f * x);
    return (e - 1.0f) / (e + 1.0f);
}

// ---------------- RY gates on packed state sp[16] (lo = even r, hi = odd r) ----------
// Wire w acts on amplitude bit (9-w): wires 0..4 -> lane bits 4..0,
// wires 5..8 -> packed-index bits 3..0, wire 9 -> intra-pair.

template<int LB>
__device__ __forceinline__ void ry_lane2(ull (&sp)[16], ull cc, ull sg2) {
#pragma unroll
    for (int q = 0; q < 16; q++) {
        ull p = __shfl_xor_sync(FULL, sp[q], 1 << LB);
        sp[q] = fma2(cc, sp[q], mul2(sg2, p));
    }
}

template<int PB>
__device__ __forceinline__ void ry_local2(ull (&sp)[16], ull cc, ull pp, ull nn) {
#pragma unroll
    for (int q = 0; q < 16; q++) {
        if (!((q >> PB) & 1)) {
            ull a0 = sp[q], a1 = sp[q + (1 << PB)];
            sp[q]             = fma2(cc, a0, mul2(nn, a1));
            sp[q + (1 << PB)] = fma2(pp, a0, mul2(cc, a1));
        }
    }
}

__device__ __forceinline__ void ry_intra(ull (&sp)[16], ull cc, ull mm) {
    // mm = (-si, +si): result = (c*s0 - si*s1, c*s1 + si*s0)
#pragma unroll
    for (int q = 0; q < 16; q++)
        sp[q] = fma2(cc, sp[q], mul2(mm, swp(sp[q])));
}

// ---------------- fused 9-CNOT entangling block ----------------
// Composed permutation (dest-centric), derived from
// even CNOTs (0,1)(2,3)(4,5)(6,7)(8,9) then odd (1,2)(3,4)(5,6)(7,8):
//   src lane bits: l4, l3^l4, l2^l3, l1^l2^l3, l0^l1
//   src reg  bits: r4^(l0^l1 of dest), r3^r4, r2^r3^r4, r1^r2, r0^r1^r2
// Sender-centric: (l0^l1) of the dest equals bit0 of the SOURCE lane, so each
// lane sends sp[QP(q) ^ (own_bit0<<3)], half-swapped iff q0^q1.
__device__ __forceinline__ constexpr int QP(int q) {
    int q3 = (q >> 3) & 1, q2 = (q >> 2) & 1, q1 = (q >> 1) & 1, q0 = q & 1;
    return (q3 << 3) | ((q2 ^ q3) << 2) | ((q1 ^ q2 ^ q3) << 1) | (q0 ^ q1);
}

__device__ __forceinline__ void cnot_block(ull (&sp)[16], int sl, bool lx) {
    ull ns[16];
#pragma unroll
    for (int q = 0; q < 16; q++) {
        const int Q = QP(q);
        ull a = lx ? sp[Q ^ 8] : sp[Q];
        if ((q ^ (q >> 1)) & 1) a = swp(a);
        ns[q] = __shfl_sync(FULL, a, sl);
    }
#pragma unroll
    for (int q = 0; q < 16; q++) sp[q] = ns[q];
}

// ---------------- kernel ----------------
__global__ __launch_bounds__(128, 4)
void hybrid_head_kernel(const float* __restrict__ X,       // (B,512)
                        const float* __restrict__ Wpre,    // (10,512)
                        const float* __restrict__ bpre,    // (10,)
                        const float* __restrict__ qp,      // (150,)
                        const float* __restrict__ Wpost,   // (2,10)
                        const float* __restrict__ bpost,   // (2,)
                        float* __restrict__ out,           // (B,2)
                        int B)
{
    __shared__ ull g_cc[6][10], g_pp[6][10], g_nn[6][10], g_mm[6];

    const int tid = threadIdx.x;
    if (tid < 60) {
        int k = tid / 10, w = tid % 10;
        float th = 0.5f * qp[(k + 1) * 10 + w];
        float c, si; sincosf(th, &si, &c);
        g_cc[k][w] = pk(c, c);
        g_pp[k][w] = pk(si, si);
        g_nn[k][w] = pk(-si, -si);
        if (w == 9) g_mm[k] = pk(-si, si);
    }
    __syncthreads();

    const int lane   = tid & 31;
    const int sample = blockIdx.x * 4 + (tid >> 5);
    if (sample >= B) return;

    // ---------------- pre-GEMM (packed accumulators) ----------------
    const float4* Xr = reinterpret_cast<const float4*>(X + (size_t)sample * 512);
    float4 xv[4];
#pragma unroll
    for (int j = 0; j < 4; j++) xv[j] = Xr[j * 32 + lane];
    ull xp[8];
#pragma unroll
    for (int j = 0; j < 4; j++) {
        xp[2 * j]     = pk(xv[j].x, xv[j].y);
        xp[2 * j + 1] = pk(xv[j].z, xv[j].w);
    }

    float acc[10];
#pragma unroll
    for (int w = 0; w < 10; w++) {
        const float4* Wr = reinterpret_cast<const float4*>(Wpre + w * 512);
        ull a2 = 0ULL;
#pragma unroll
        for (int j = 0; j < 4; j++) {
            float4 wv = Wr[j * 32 + lane];
            a2 = fma2(xp[2 * j],     pk(wv.x, wv.y), a2);
            a2 = fma2(xp[2 * j + 1], pk(wv.z, wv.w), a2);
        }
        float lo, hi; upk(a2, lo, hi);
        acc[w] = lo + hi;
    }
#pragma unroll
    for (int w = 0; w < 10; w++) {
#pragma unroll
        for (int o = 16; o > 0; o >>= 1)
            acc[w] += __shfl_xor_sync(FULL, acc[w], o);
    }

    // lane w (w<10) owns wire w's angle
    float myc, mys;
    {
        float x = acc[0] + bpre[0];
#pragma unroll
        for (int w = 1; w < 10; w++) {
            float xw = acc[w] + bpre[w];
            x = (lane == w) ? xw : x;
        }
        float th = fast_tanh(x) * PI_4;      // theta/2
        myc = __cosf(th);
        mys = __sinf(th);
    }

    // ---------------- quantum circuit ----------------
    ull sp[16];
    const ull init = pk(0.03125f, 0.03125f);   // H^{x10}|0..0>
#pragma unroll
    for (int q = 0; q < 16; q++) sp[q] = init;

    // per-sample RY layer (gate-by-gate, coefs from owning lanes)
    {
        float cw, sw, sg;
        cw = __shfl_sync(FULL, myc, 0); sw = __shfl_sync(FULL, mys, 0);
        sg = ((lane >> 4) & 1) ? sw : -sw;  ry_lane2<4>(sp, pk(cw, cw), pk(sg, sg));
        cw = __shfl_sync(FULL, myc, 1); sw = __shfl_sync(FULL, mys, 1);
        sg = ((lane >> 3) & 1) ? sw : -sw;  ry_lane2<3>(sp, pk(cw, cw), pk(sg, sg));
        cw = __shfl_sync(FULL, myc, 2); sw = __shfl_sync(FULL, mys, 2);
        sg = ((lane >> 2) & 1) ? sw : -sw;  ry_lane2<2>(sp, pk(cw, cw), pk(sg, sg));
        cw = __shfl_sync(FULL, myc, 3); sw = __shfl_sync(FULL, mys, 3);
        sg = ((lane >> 1) & 1) ? sw : -sw;  ry_lane2<1>(sp, pk(cw, cw), pk(sg, sg));
        cw = __shfl_sync(FULL, myc, 4); sw = __shfl_sync(FULL, mys, 4);
        sg = (lane & 1) ? sw : -sw;         ry_lane2<0>(sp, pk(cw, cw), pk(sg, sg));
        cw = __shfl_sync(FULL, myc, 5); sw = __shfl_sync(FULL, mys, 5);
        ry_local2<3>(sp, pk(cw, cw), pk(sw, sw), pk(-sw, -sw));
        cw = __shfl_sync(FULL, myc, 6); sw = __shfl_sync(FULL, mys, 6);
        ry_local2<2>(sp, pk(cw, cw), pk(sw, sw), pk(-sw, -sw));
        cw = __shfl_sync(FULL, myc, 7); sw = __shfl_sync(FULL, mys, 7);
        ry_local2<1>(sp, pk(cw, cw), pk(sw, sw), pk(-sw, -sw));
        cw = __shfl_sync(FULL, myc, 8); sw = __shfl_sync(FULL, mys, 8);
        ry_local2<0>(sp, pk(cw, cw), pk(sw, sw), pk(-sw, -sw));
        cw = __shfl_sync(FULL, myc, 9); sw = __shfl_sync(FULL, mys, 9);
        ry_intra(sp, pk(cw, cw), pk(-sw, sw));
    }

    // source lane of the fused CNOT permutation
    const int l4 = (lane >> 4) & 1, l3 = (lane >> 3) & 1, l2 = (lane >> 2) & 1,
              l1 = (lane >> 1) & 1, l0 = lane & 1;
    const int sl = (l4 << 4) | ((l3 ^ l4) << 3) | ((l2 ^ l3) << 2) |
                   ((l1 ^ l2 ^ l3) << 1) | (l0 ^ l1);
    const bool lx = l0;

#pragma unroll 1
    for (int k = 0; k < 6; k++) {
        cnot_block(sp, sl, lx);
        // shared RY layer k (row k+1 of q_params)
        ry_lane2<4>(sp, g_cc[k][0], l4 ? g_pp[k][0] : g_nn[k][0]);
        ry_lane2<3>(sp, g_cc[k][1], l3 ? g_pp[k][1] : g_nn[k][1]);
        ry_lane2<2>(sp, g_cc[k][2], l2 ? g_pp[k][2] : g_nn[k][2]);
        ry_lane2<1>(sp, g_cc[k][3], l1 ? g_pp[k][3] : g_nn[k][3]);
        ry_lane2<0>(sp, g_cc[k][4], l0 ? g_pp[k][4] : g_nn[k][4]);
        ry_local2<3>(sp, g_cc[k][5], g_pp[k][5], g_nn[k][5]);
        ry_local2<2>(sp, g_cc[k][6], g_pp[k][6], g_nn[k][6]);
        ry_local2<1>(sp, g_cc[k][7], g_pp[k][7], g_nn[k][7]);
        ry_local2<0>(sp, g_cc[k][8], g_pp[k][8], g_nn[k][8]);
        ry_intra(sp, g_cc[k][9], g_mm[k]);
    }

    // ---------------- <Z_w> via signed-sum tree over probs ----------------
    float s[32];
#pragma unroll
    for (int q = 0; q < 16; q++) upk(sp[q], s[2 * q], s[2 * q + 1]);

    float p[32];
#pragma unroll
    for (int r = 0; r < 32; r++) p[r] = s[r] * s[r];

    float a16[16], a8[8], a4[4], a2[2];
    float zb0 = 0.f, zb1 = 0.f, zb2 = 0.f, zb3 = 0.f;
#pragma unroll
    for (int i = 0; i < 16; i++) { a16[i] = p[2*i] + p[2*i+1]; zb0 += p[2*i] - p[2*i+1]; }
#pragma unroll
    for (int i = 0; i < 8;  i++) { a8[i]  = a16[2*i] + a16[2*i+1]; zb1 += a16[2*i] - a16[2*i+1]; }
#pragma unroll
    for (int i = 0; i < 4;  i++) { a4[i]  = a8[2*i] + a8[2*i+1];  zb2 += a8[2*i] - a8[2*i+1]; }
#pragma unroll
    for (int i = 0; i < 2;  i++) { a2[i]  = a4[2*i] + a4[2*i+1];  zb3 += a4[2*i] - a4[2*i+1]; }
    float T   = a2[0] + a2[1];
    float zb4 = a2[0] - a2[1];

    float z[10];
    z[0] = (lane & 16) ? -T : T;
    z[1] = (lane & 8)  ? -T : T;
    z[2] = (lane & 4)  ? -T : T;
    z[3] = (lane & 2)  ? -T : T;
    z[4] = (lane & 1)  ? -T : T;
    z[5] = zb4;
    z[6] = zb3;
    z[7] = zb2;
    z[8] = zb1;
    z[9] = zb0;

#pragma unroll
    for (int w = 0; w < 10; w++) {
#pragma unroll
        for (int o = 16; o > 0; o >>= 1)
            z[w] += __shfl_xor_sync(FULL, z[w], o);
    }

    // ---------------- post-GEMM ----------------
    if (lane == 0) {
        float o0 = bpost[0], o1 = bpost[1];
#pragma unroll
        for (int w = 0; w < 10; w++) {
            o0 = fmaf(z[w], Wpost[w],      o0);
            o1 = fmaf(z[w], Wpost[10 + w], o1);
        }
        reinterpret_cast<float2*>(out)[sample] = make_float2(o0, o1);
    }
}

extern "C" void kernel_launch(void* const* d_in, const int* in_sizes, int n_in,
                              void* d_out, int out_size)
{
    const float* X     = (const float*)d_in[0];
    const float* Wpre  = (const float*)d_in[1];
    const float* bpre  = (const float*)d_in[2];
    const float* qp    = (const float*)d_in[3];
    const float* Wpost = (const float*)d_in[4];
    const float* bpost = (const float*)d_in[5];
    float* out = (float*)d_out;

    int B = in_sizes[0] / 512;           // 8192
    int blocks = (B + 3) / 4;            // 4 samples (warps) per 128-thread block
    hybrid_head_kernel<<<blocks, 128>>>(X, Wpre, bpre, qp, Wpost, bpost, out, B);
}

// round 6
// speedup vs baseline: 1.3471x; 1.1289x over previous
#include <cuda_runtime.h>

typedef unsigned long long ull;
#define FULL 0xffffffffu
#define PI_4 0.78539816339744830962f

// ---------------- packed f32x2 helpers ----------------
__device__ __forceinline__ ull pk(float a, float b) {
    ull r; asm("mov.b64 %0, {%1,%2};" : "=l"(r) : "f"(a), "f"(b)); return r;
}
__device__ __forceinline__ void upk(ull v, float &a, float &b) {
    asm("mov.b64 {%0,%1}, %2;" : "=f"(a), "=f"(b) : "l"(v));
}
__device__ __forceinline__ ull fma2(ull a, ull b, ull c) {
    ull d; asm("fma.rn.f32x2 %0, %1, %2, %3;" : "=l"(d) : "l"(a), "l"(b), "l"(c)); return d;
}
__device__ __forceinline__ ull swp(ull v) {            // swap packed halves
    unsigned lo = (unsigned)v, hi = (unsigned)(v >> 32);
    return ((ull)lo << 32) | hi;
}

__device__ __forceinline__ float fast_tanh(float x) {
    float e = __expf(2.0f * x);
    return (e - 1.0f) / (e + 1.0f);
}

// ---------------- tan-form RY gates on packed state sp[16] ----------------
// RY(theta) = cos(t2)*(I + tan(t2)*K); cos factors are folded into the initial
// amplitude, so each gate is a single FFMA2 per packed pair.
// Wire w acts on amplitude bit (9-w): wires 0..4 -> lane bits 4..0,
// wires 5..8 -> packed-index bits 3..0, wire 9 -> intra-pair.

template<int LB>
__device__ __forceinline__ void ry_lane_t(ull (&sp)[16], ull tl) {
    // s' = s + (bit ? +t : -t) * partner   (sign pre-folded into tl)
#pragma unroll
    for (int q = 0; q < 16; q++) {
        ull p = __shfl_xor_sync(FULL, sp[q], 1 << LB);
        sp[q] = fma2(tl, p, sp[q]);
    }
}

template<int PB>
__device__ __forceinline__ void ry_local_t(ull (&sp)[16], ull pt, ull nt) {
#pragma unroll
    for (int q = 0; q < 16; q++) {
        if (!((q >> PB) & 1)) {
            ull a0 = sp[q], a1 = sp[q + (1 << PB)];
            sp[q]             = fma2(nt, a1, a0);   // a0 - t*a1
            sp[q + (1 << PB)] = fma2(pt, a0, a1);   // a1 + t*a0 (old a0)
        }
    }
}

__device__ __forceinline__ void ry_intra_t(ull (&sp)[16], ull mt) {
    // mt = (-t, +t): lo' = lo - t*hi, hi' = hi + t*lo
#pragma unroll
    for (int q = 0; q < 16; q++)
        sp[q] = fma2(mt, swp(sp[q]), sp[q]);
}

// ---------------- fused 9-CNOT entangling block ----------------
// src lane bits: l4, l3^l4, l2^l3, l1^l2^l3, l0^l1
// src reg  bits: r4^(l0^l1 of dest), r3^r4, r2^r3^r4, r1^r2, r0^r1^r2
// (l0^l1) of the dest equals bit0 of the SOURCE lane, so each lane sends
// sp[QP(q) ^ (own_bit0<<3)], half-swapped iff q0^q1.
__device__ __forceinline__ constexpr int QP(int q) {
    int q3 = (q >> 3) & 1, q2 = (q >> 2) & 1, q1 = (q >> 1) & 1, q0 = q & 1;
    return (q3 << 3) | ((q2 ^ q3) << 2) | ((q1 ^ q2 ^ q3) << 1) | (q0 ^ q1);
}

__device__ __forceinline__ void cnot_block(ull (&sp)[16], int sl, bool lx) {
    ull ns[16];
#pragma unroll
    for (int q = 0; q < 16; q++) {
        const int Q = QP(q);
        ull a = lx ? sp[Q ^ 8] : sp[Q];
        if ((q ^ (q >> 1)) & 1) a = swp(a);
        ns[q] = __shfl_sync(FULL, a, sl);
    }
#pragma unroll
    for (int q = 0; q < 16; q++) sp[q] = ns[q];
}

// ---------------- kernel ----------------
__global__ __launch_bounds__(128, 4)
void hybrid_head_kernel(const float* __restrict__ X,       // (B,512)
                        const float* __restrict__ Wpre,    // (10,512)
                        const float* __restrict__ bpre,    // (10,)
                        const float* __restrict__ qp,      // (150,)
                        const float* __restrict__ Wpost,   // (2,10)
                        const float* __restrict__ bpost,   // (2,)
                        float* __restrict__ out,           // (B,2)
                        int B)
{
    __shared__ ull g_tp[6][10], g_tn[6][10], g_tm[6];
    __shared__ float g_cos[60];
    __shared__ float g_Cs;                    // product of the 60 shared cosines

    const int tid = threadIdx.x;
    if (tid < 60) {
        int k = tid / 10, w = tid % 10;
        float th = 0.5f * qp[(k + 1) * 10 + w];
        float c = cosf(th), t = tanf(th);
        g_tp[k][w] = pk(t, t);
        g_tn[k][w] = pk(-t, -t);
        g_cos[tid] = c;
        if (w == 9) g_tm[k] = pk(-t, t);
    }
    __syncthreads();
    if (tid == 0) {
        float prod = 1.0f;
#pragma unroll
        for (int i = 0; i < 60; i++) prod *= g_cos[i];
        g_Cs = prod;
    }
    __syncthreads();

    const int lane   = tid & 31;
    const int sample = blockIdx.x * 4 + (tid >> 5);
    if (sample >= B) return;

    // ---------------- pre-GEMM (packed accumulators) ----------------
    const float4* Xr = reinterpret_cast<const float4*>(X + (size_t)sample * 512);
    float4 xv[4];
#pragma unroll
    for (int j = 0; j < 4; j++) xv[j] = Xr[j * 32 + lane];
    ull xp[8];
#pragma unroll
    for (int j = 0; j < 4; j++) {
        xp[2 * j]     = pk(xv[j].x, xv[j].y);
        xp[2 * j + 1] = pk(xv[j].z, xv[j].w);
    }

    float acc[10];
#pragma unroll
    for (int w = 0; w < 10; w++) {
        const float4* Wr = reinterpret_cast<const float4*>(Wpre + w * 512);
        ull a2 = 0ULL;
#pragma unroll
        for (int j = 0; j < 4; j++) {
            float4 wv = Wr[j * 32 + lane];
            a2 = fma2(xp[2 * j],     pk(wv.x, wv.y), a2);
            a2 = fma2(xp[2 * j + 1], pk(wv.z, wv.w), a2);
        }
        float lo, hi; upk(a2, lo, hi);
        acc[w] = lo + hi;
    }
#pragma unroll
    for (int w = 0; w < 10; w++) {
#pragma unroll
        for (int o = 16; o > 0; o >>= 1)
            acc[w] += __shfl_xor_sync(FULL, acc[w], o);
    }

    // lane w (w<10) owns wire w's angle
    float myc, myt;
    {
        float x = acc[0] + bpre[0];
#pragma unroll
        for (int w = 1; w < 10; w++) {
            float xw = acc[w] + bpre[w];
            x = (lane == w) ? xw : x;
        }
        float th = fast_tanh(x) * PI_4;      // theta/2, |th| <= pi/4
        myc = __cosf(th);
        myt = __tanf(th);                    // |t| <= 1
    }

    // product of the 10 per-sample cosines (masked butterfly)
    float pc = (lane < 10) ? myc : 1.0f;
#pragma unroll
    for (int o = 16; o > 0; o >>= 1)
        pc *= __shfl_xor_sync(FULL, pc, o);

    // ---------------- quantum circuit ----------------
    ull sp[16];
    {
        float A = pc * g_Cs * 0.03125f;      // all cos factors * H^{x10} init
        const ull init = pk(A, A);
#pragma unroll
        for (int q = 0; q < 16; q++) sp[q] = init;
    }

    const int l4 = (lane >> 4) & 1, l3 = (lane >> 3) & 1, l2 = (lane >> 2) & 1,
              l1 = (lane >> 1) & 1, l0 = lane & 1;

    // per-sample RY layer (tan coefficients broadcast from owning lanes)
    {
        float tw, ts;
        tw = __shfl_sync(FULL, myt, 0); ts = l4 ? tw : -tw; ry_lane_t<4>(sp, pk(ts, ts));
        tw = __shfl_sync(FULL, myt, 1); ts = l3 ? tw : -tw; ry_lane_t<3>(sp, pk(ts, ts));
        tw = __shfl_sync(FULL, myt, 2); ts = l2 ? tw : -tw; ry_lane_t<2>(sp, pk(ts, ts));
        tw = __shfl_sync(FULL, myt, 3); ts = l1 ? tw : -tw; ry_lane_t<1>(sp, pk(ts, ts));
        tw = __shfl_sync(FULL, myt, 4); ts = l0 ? tw : -tw; ry_lane_t<0>(sp, pk(ts, ts));
        tw = __shfl_sync(FULL, myt, 5); ry_local_t<3>(sp, pk(tw, tw), pk(-tw, -tw));
        tw = __shfl_sync(FULL, myt, 6); ry_local_t<2>(sp, pk(tw, tw), pk(-tw, -tw));
        tw = __shfl_sync(FULL, myt, 7); ry_local_t<1>(sp, pk(tw, tw), pk(-tw, -tw));
        tw = __shfl_sync(FULL, myt, 8); ry_local_t<0>(sp, pk(tw, tw), pk(-tw, -tw));
        tw = __shfl_sync(FULL, myt, 9); ry_intra_t(sp, pk(-tw, tw));
    }

    // source lane of the fused CNOT permutation
    const int sl = (l4 << 4) | ((l3 ^ l4) << 3) | ((l2 ^ l3) << 2) |
                   ((l1 ^ l2 ^ l3) << 1) | (l0 ^ l1);
    const bool lx = l0;

#pragma unroll 1
    for (int k = 0; k < 6; k++) {
        cnot_block(sp, sl, lx);
        // shared RY layer k (row k+1 of q_params), tan form
        ry_lane_t<4>(sp, l4 ? g_tp[k][0] : g_tn[k][0]);
        ry_lane_t<3>(sp, l3 ? g_tp[k][1] : g_tn[k][1]);
        ry_lane_t<2>(sp, l2 ? g_tp[k][2] : g_tn[k][2]);
        ry_lane_t<1>(sp, l1 ? g_tp[k][3] : g_tn[k][3]);
        ry_lane_t<0>(sp, l0 ? g_tp[k][4] : g_tn[k][4]);
        ry_local_t<3>(sp, g_tp[k][5], g_tn[k][5]);
        ry_local_t<2>(sp, g_tp[k][6], g_tn[k][6]);
        ry_local_t<1>(sp, g_tp[k][7], g_tn[k][7]);
        ry_local_t<0>(sp, g_tp[k][8], g_tn[k][8]);
        ry_intra_t(sp, g_tm[k]);
    }

    // ---------------- <Z_w> via signed-sum tree over probs ----------------
    float s[32];
#pragma unroll
    for (int q = 0; q < 16; q++) upk(sp[q], s[2 * q], s[2 * q + 1]);

    float p[32];
#pragma unroll
    for (int r = 0; r < 32; r++) p[r] = s[r] * s[r];

    float a16[16], a8[8], a4[4], a2[2];
    float zb0 = 0.f, zb1 = 0.f, zb2 = 0.f, zb3 = 0.f;
#pragma unroll
    for (int i = 0; i < 16; i++) { a16[i] = p[2*i] + p[2*i+1]; zb0 += p[2*i] - p[2*i+1]; }
#pragma unroll
    for (int i = 0; i < 8;  i++) { a8[i]  = a16[2*i] + a16[2*i+1]; zb1 += a16[2*i] - a16[2*i+1]; }
#pragma unroll
    for (int i = 0; i < 4;  i++) { a4[i]  = a8[2*i] + a8[2*i+1];  zb2 += a8[2*i] - a8[2*i+1]; }
#pragma unroll
    for (int i = 0; i < 2;  i++) { a2[i]  = a4[2*i] + a4[2*i+1];  zb3 += a4[2*i] - a4[2*i+1]; }
    float T   = a2[0] + a2[1];
    float zb4 = a2[0] - a2[1];

    float z[10];
    z[0] = (lane & 16) ? -T : T;
    z[1] = (lane & 8)  ? -T : T;
    z[2] = (lane & 4)  ? -T : T;
    z[3] = (lane & 2)  ? -T : T;
    z[4] = (lane & 1)  ? -T : T;
    z[5] = zb4;
    z[6] = zb3;
    z[7] = zb2;
    z[8] = zb1;
    z[9] = zb0;

#pragma unroll
    for (int w = 0; w < 10; w++) {
#pragma unroll
        for (int o = 16; o > 0; o >>= 1)
            z[w] += __shfl_xor_sync(FULL, z[w], o);
    }

    // ---------------- post-GEMM ----------------
    if (lane == 0) {
        float o0 = bpost[0], o1 = bpost[1];
#pragma unroll
        for (int w = 0; w < 10; w++) {
            o0 = fmaf(z[w], Wpost[w],      o0);
            o1 = fmaf(z[w], Wpost[10 + w], o1);
        }
        reinterpret_cast<float2*>(out)[sample] = make_float2(o0, o1);
    }
}

extern "C" void kernel_launch(void* const* d_in, const int* in_sizes, int n_in,
                              void* d_out, int out_size)
{
    const float* X     = (const float*)d_in[0];
    const float* Wpre  = (const float*)d_in[1];
    const float* bpre  = (const float*)d_in[2];
    const float* qp    = (const float*)d_in[3];
    const float* Wpost = (const float*)d_in[4];
    const float* bpost = (const float*)d_in[5];
    float* out = (float*)d_out;

    int B = in_sizes[0] / 512;           // 8192
    int blocks = (B + 3) / 4;            // 4 samples (warps) per 128-thread block
    hybrid_head_kernel<<<blocks, 128>>>(X, Wpre, bpre, qp, Wpost, bpost, out, B);
}